// round 1
// baseline (speedup 1.0000x reference)
#include <cuda_runtime.h>
#include <cuda_bf16.h>
#include <math.h>

// Problem constants (fixed shapes from reference)
#define NN 50000
#define EE 800000
#define DD 256
#define MM 64
#define RR 12

// Scratch (no cudaMalloc allowed)
__device__ float g_tmp[NN * DD];   // FC intermediate
__device__ float g_v[NN * MM];     // v = x @ Wv
__device__ float g_agg[NN * MM];   // scatter accumulator
__device__ float g_rbf[EE * RR];   // radial basis

__device__ __forceinline__ float gelu_f(float x) {
    // JAX approximate (tanh) GELU
    float x3 = x * x * x;
    float t = tanhf(0.7978845608028654f * (x + 0.044715f * x3));
    return 0.5f * x * (1.0f + t);
}

// ---------------------------------------------------------------------------
// Embedding init: x[n,d] = sum_h table[z[n],h] * W[h,d] + b[d]
// ---------------------------------------------------------------------------
__global__ void embed_kernel(const int* __restrict__ z,
                             const float* __restrict__ table,
                             const float* __restrict__ W,
                             const float* __restrict__ b,
                             float* __restrict__ x, int N) {
    int n = blockIdx.x;
    if (n >= N) return;
    int d = threadIdx.x;  // 256 threads
    int t = z[n];
    float acc = b[d];
#pragma unroll
    for (int h = 0; h < 5; h++) acc += table[t * 5 + h] * W[h * 256 + d];
    x[(size_t)n * 256 + d] = acc;
}

// ---------------------------------------------------------------------------
// Tiled SGEMM: C[rows x ncols] = op(A[rows x K] @ B[K x ncols])
// BM=BN=64, BK=16, 256 threads, 4x4 per thread.
// Epilogue: optional bias add, GELU, residual add (reads C before writing).
// ---------------------------------------------------------------------------
template <bool BIAS, bool GELU, bool RESID>
__global__ void sgemm64(const float* __restrict__ A,
                        const float* __restrict__ B,
                        const float* __restrict__ bias,
                        float* __restrict__ C,
                        int rows, int K, int ncols) {
    const int BM = 64, BN = 64, BK = 16;
    __shared__ float As[BK][BM + 1];
    __shared__ float Bs[BK][BN];

    int tid = threadIdx.x;
    int tr = tid >> 4;        // 0..15
    int tc = tid & 15;        // 0..15
    int r0 = blockIdx.y * BM;
    int c0 = blockIdx.x * BN;

    // A-tile load mapping: 64 rows x 16 cols, float4 per thread
    int la_r = tid >> 2;            // 0..63
    int la_c = (tid & 3) * 4;       // 0,4,8,12
    // B-tile load mapping: 16 rows x 64 cols, float4 per thread
    int lb_r = tid >> 4;            // 0..15
    int lb_c = (tid & 15) * 4;      // 0..60

    float acc[4][4] = {};

    for (int k0 = 0; k0 < K; k0 += BK) {
        int ar = r0 + la_r;
        float4 av = make_float4(0.f, 0.f, 0.f, 0.f);
        if (ar < rows)
            av = *reinterpret_cast<const float4*>(A + (size_t)ar * K + k0 + la_c);
        As[la_c + 0][la_r] = av.x;
        As[la_c + 1][la_r] = av.y;
        As[la_c + 2][la_r] = av.z;
        As[la_c + 3][la_r] = av.w;

        float4 bv = *reinterpret_cast<const float4*>(
            B + (size_t)(k0 + lb_r) * ncols + c0 + lb_c);
        *reinterpret_cast<float4*>(&Bs[lb_r][lb_c]) = bv;

        __syncthreads();

#pragma unroll
        for (int kk = 0; kk < BK; kk++) {
            float am[4];
            float4 bn4 = *reinterpret_cast<const float4*>(&Bs[kk][tc * 4]);
            float bn[4] = {bn4.x, bn4.y, bn4.z, bn4.w};
#pragma unroll
            for (int i = 0; i < 4; i++) am[i] = As[kk][tr * 4 + i];
#pragma unroll
            for (int i = 0; i < 4; i++)
#pragma unroll
                for (int j = 0; j < 4; j++)
                    acc[i][j] = fmaf(am[i], bn[j], acc[i][j]);
        }
        __syncthreads();
    }

#pragma unroll
    for (int i = 0; i < 4; i++) {
        int row = r0 + tr * 4 + i;
        if (row >= rows) continue;
#pragma unroll
        for (int j = 0; j < 4; j++) {
            int col = c0 + tc * 4 + j;
            float val = acc[i][j];
            if (BIAS) val += bias[col];
            if (GELU) val = gelu_f(val);
            if (RESID) val += C[(size_t)row * ncols + col];
            C[(size_t)row * ncols + col] = val;
        }
    }
}

// ---------------------------------------------------------------------------
// Bessel RBF with polynomial envelope (p=5)
// ---------------------------------------------------------------------------
__global__ void rbf_kernel(const int* __restrict__ ei,
                           const float* __restrict__ pos,
                           const float* __restrict__ freqs,
                           int E) {
    int e = blockIdx.x * blockDim.x + threadIdx.x;
    if (e >= E) return;
    int i = ei[e];
    int j = ei[E + e];
    float dx = pos[i * 3 + 0] - pos[j * 3 + 0];
    float dy = pos[i * 3 + 1] - pos[j * 3 + 1];
    float dz = pos[i * 3 + 2] - pos[j * 3 + 2];
    float dist = sqrtf(dx * dx + dy * dy + dz * dz + 1e-12f);
    float x = dist * 0.2f;  // dist / CUTOFF
    float x2 = x * x;
    float x4 = x2 * x2;
    // p=5: a=-(6*7)/2=-21, b=5*7=35, c=-(5*6)/2=-15
    float env = 1.0f / x + (-21.0f) * x4 + 35.0f * x4 * x + (-15.0f) * x4 * x2;
#pragma unroll
    for (int r = 0; r < 12; r++)
        g_rbf[(size_t)e * 12 + r] = env * sinf(freqs[r] * x);
}

// ---------------------------------------------------------------------------
// Edge messages + scatter-add: one warp per edge.
// g[m] = sum_r rbf[e,r] * Wrbf[r,m];  atomicAdd(agg[i,m], v[j,m]*g[m])
// ---------------------------------------------------------------------------
__global__ void edge_msg_kernel(const int* __restrict__ ei,
                                const float* __restrict__ Wrbf,  // [12,64]
                                int E) {
    __shared__ float sW[12 * 64];
    for (int t = threadIdx.x; t < 12 * 64; t += blockDim.x) sW[t] = Wrbf[t];
    __syncthreads();

    int warp = (blockIdx.x * blockDim.x + threadIdx.x) >> 5;
    int lane = threadIdx.x & 31;
    if (warp >= E) return;

    int i = ei[warp];
    int j = ei[E + warp];

    float rv[12];
#pragma unroll
    for (int r = 0; r < 12; r++) rv[r] = __ldg(&g_rbf[(size_t)warp * 12 + r]);

#pragma unroll
    for (int h = 0; h < 2; h++) {
        int m = lane + h * 32;
        float g = 0.f;
#pragma unroll
        for (int r = 0; r < 12; r++) g = fmaf(rv[r], sW[r * 64 + m], g);
        float val = g_v[(size_t)j * 64 + m] * g;
        atomicAdd(&g_agg[(size_t)i * 64 + m], val);
    }
}

// ---------------------------------------------------------------------------
// Launcher
// ---------------------------------------------------------------------------
extern "C" void kernel_launch(void* const* d_in, const int* in_sizes, int n_in,
                              void* d_out, int out_size) {
    const int* z = (const int*)d_in[0];
    const float* pos = (const float*)d_in[1];
    const int* ei = (const int*)d_in[4];
    const float* emb_table = (const float*)d_in[5];
    const float* emb_W = (const float*)d_in[6];
    const float* emb_b = (const float*)d_in[7];
    const float* freqs = (const float*)d_in[8];
    const float* fc0_W = (const float*)d_in[9];
    const float* fc0_b = (const float*)d_in[10];
    const float* conv_Wv = (const float*)d_in[11];
    const float* conv_Wrbf = (const float*)d_in[12];
    const float* conv_Wout = (const float*)d_in[13];
    const float* fc_W = (const float*)d_in[14];
    const float* fc_b = (const float*)d_in[15];

    int N = in_sizes[1] / 3;   // 50000
    int E = in_sizes[4] / 2;   // 800000

    float* x = (float*)d_out;

    float *tmp, *vbuf, *agg;
    cudaGetSymbolAddress((void**)&tmp, g_tmp);
    cudaGetSymbolAddress((void**)&vbuf, g_v);
    cudaGetSymbolAddress((void**)&agg, g_agg);

    const int GEMM_THREADS = 256;
    dim3 gridD((256 + 63) / 64, (N + 63) / 64);  // ncols=256
    dim3 gridM((64 + 63) / 64, (N + 63) / 64);   // ncols=64

    // 1. init embedding
    embed_kernel<<<N, 256>>>(z, emb_table, emb_W, emb_b, x, N);

    // 2. init FC block (no residual): x = gelu(gelu(x@W0+b0)@W1+b1)
    sgemm64<true, true, false><<<gridD, GEMM_THREADS>>>(x, fc0_W, fc0_b, tmp, N, 256, 256);
    sgemm64<true, true, false><<<gridD, GEMM_THREADS>>>(tmp, fc0_W + 256 * 256, fc0_b + 256, x, N, 256, 256);

    // 3. radial basis
    rbf_kernel<<<(E + 255) / 256, 256>>>(ei, pos, freqs, E);

    // 4. interaction blocks
    for (int n = 0; n < 4; n++) {
        cudaMemsetAsync(agg, 0, (size_t)N * 64 * sizeof(float));

        // v = x @ Wv[n]
        sgemm64<false, false, false><<<gridM, GEMM_THREADS>>>(
            x, conv_Wv + (size_t)n * 256 * 64, nullptr, vbuf, N, 256, 64);

        // gated messages + scatter-add (warp per edge, 8 warps per block)
        edge_msg_kernel<<<(E + 7) / 8, 256>>>(ei, conv_Wrbf + (size_t)n * 12 * 64, E);

        // x = x + agg @ Wout[n]
        sgemm64<false, false, true><<<gridD, GEMM_THREADS>>>(
            agg, conv_Wout + (size_t)n * 64 * 256, nullptr, x, N, 64, 256);

        // x = x + fc_block(x)
        const float* W0 = fc_W + (size_t)n * 2 * 256 * 256;
        const float* W1 = W0 + 256 * 256;
        const float* b0 = fc_b + (size_t)n * 2 * 256;
        const float* b1 = b0 + 256;
        sgemm64<true, true, false><<<gridD, GEMM_THREADS>>>(x, W0, b0, tmp, N, 256, 256);
        sgemm64<true, true, true><<<gridD, GEMM_THREADS>>>(tmp, W1, b1, x, N, 256, 256);
    }
}

// round 3
// speedup vs baseline: 2.0402x; 2.0402x over previous
#include <cuda_runtime.h>
#include <cuda_bf16.h>
#include <math.h>
#include <stdint.h>

#define NN 50000
#define EE 800000

// ---------------- scratch (no cudaMalloc allowed) ----------------
__device__ float g_tmp[NN * 256];
__device__ float g_v[NN * 64];
__device__ float g_agg[NN * 64];
__device__ float g_rbf[EE * 12];
// bf16 hi/lo transposed weights: 10x[256x256] + 8x[64x256 / 256x64]
__device__ __nv_bfloat16 g_wh[10 * 65536 + 8 * 16384];
__device__ __nv_bfloat16 g_wl[10 * 65536 + 8 * 16384];

__device__ __forceinline__ uint32_t smem_u32(const void* p) {
    uint32_t a;
    asm("{ .reg .u64 t; cvta.to.shared.u64 t, %1; cvt.u32.u64 %0, t; }" : "=r"(a) : "l"(p));
    return a;
}

__device__ __forceinline__ void ldsm4(uint32_t& r0, uint32_t& r1, uint32_t& r2,
                                      uint32_t& r3, uint32_t addr) {
    asm volatile("ldmatrix.sync.aligned.m8n8.x4.shared.b16 {%0,%1,%2,%3}, [%4];"
                 : "=r"(r0), "=r"(r1), "=r"(r2), "=r"(r3) : "r"(addr));
}

__device__ __forceinline__ void mma_bf16(float* c, const uint32_t* a, const uint32_t* b) {
    asm volatile(
        "mma.sync.aligned.m16n8k16.row.col.f32.bf16.bf16.f32 "
        "{%0,%1,%2,%3}, {%4,%5,%6,%7}, {%8,%9}, {%0,%1,%2,%3};"
        : "+f"(c[0]), "+f"(c[1]), "+f"(c[2]), "+f"(c[3])
        : "r"(a[0]), "r"(a[1]), "r"(a[2]), "r"(a[3]), "r"(b[0]), "r"(b[1]));
}

__device__ __forceinline__ float gelu_f(float x) {
    float x3 = x * x * x;
    float t = tanhf(0.7978845608028654f * (x + 0.044715f * x3));
    return 0.5f * x * (1.0f + t);
}

// ---------------------------------------------------------------------------
// Weight convert: W [nm][K x N] fp32 -> out [nm][N x K] bf16 hi/lo (transposed)
// ---------------------------------------------------------------------------
__global__ void conv_w_kernel(const float* __restrict__ W,
                              __nv_bfloat16* __restrict__ oh,
                              __nv_bfloat16* __restrict__ ol,
                              int K, int Ncols, int total) {
    int idx = blockIdx.x * blockDim.x + threadIdx.x;
    if (idx >= total) return;
    int kn = K * Ncols;
    int m = idx / kn;
    int r = idx - m * kn;
    int n = r / K;
    int k = r - n * K;
    float w = W[(size_t)m * kn + (size_t)k * Ncols + n];
    __nv_bfloat16 h = __float2bfloat16(w);
    oh[idx] = h;
    ol[idx] = __float2bfloat16(w - __bfloat162float(h));
}

// ---------------------------------------------------------------------------
// HMMA GEMM: C[rows x ncols] = epi(A[rows x K] @ W), W pre-split bf16 hi/lo,
// transposed [ncols x K]. CTA tile 128x64, BK=32, 8 warps (32x32 each).
// 3-product split: Ah*Bh + Ah*Bl + Al*Bh, fp32 accumulate.
// ---------------------------------------------------------------------------
template <bool BIAS, bool GELU, bool RESID>
__global__ void __launch_bounds__(256) mma_gemm(
    const float* __restrict__ A,
    const __nv_bfloat16* __restrict__ Bh_g,
    const __nv_bfloat16* __restrict__ Bl_g,
    const float* __restrict__ bias,
    float* __restrict__ C,
    int rows, int K, int ncols)
{
    constexpr int BM = 128, BN = 64, BK = 32, LD = 40;  // LD in bf16 elems
    __shared__ __nv_bfloat16 sAh[BM * LD];
    __shared__ __nv_bfloat16 sAl[BM * LD];
    __shared__ __nv_bfloat16 sBh[BN * LD];
    __shared__ __nv_bfloat16 sBl[BN * LD];

    int tid = threadIdx.x;
    int lane = tid & 31;
    int wid = tid >> 5;
    int wm = wid & 3;      // 0..3 -> m offset wm*32
    int wn = wid >> 2;     // 0..1 -> n offset wn*32
    int r0 = blockIdx.y * BM;
    int c0 = blockIdx.x * BN;

    float acc[2][4][4];
#pragma unroll
    for (int i = 0; i < 2; i++)
#pragma unroll
        for (int j = 0; j < 4; j++)
#pragma unroll
            for (int k = 0; k < 4; k++) acc[i][j][k] = 0.f;

    uint32_t aH = smem_u32(sAh), aL = smem_u32(sAl);
    uint32_t bH = smem_u32(sBh), bL = smem_u32(sBl);

    // ldmatrix lane-address components
    int a_r = lane & 15;              // row within 16x16 A tile
    int a_c = (lane >> 4) * 8;        // col-8 group
    int b_n = ((lane >> 4) * 8) + (lane & 7);  // n row within 16-row B pair
    int b_k = ((lane >> 3) & 1) * 8;           // k-8 group

    int nkc = K / BK;
    for (int kc = 0; kc < nkc; kc++) {
        int k0 = kc * BK;
        // --- stage A [128 x 32] fp32 -> bf16 hi/lo ---
        {
            int c4 = tid & 7;         // float4 index in row
            int rr = tid >> 3;        // 0..31
#pragma unroll
            for (int q = 0; q < 4; q++) {
                int row = rr + q * 32;
                int gr = r0 + row;
                float4 a = make_float4(0.f, 0.f, 0.f, 0.f);
                if (gr < rows)
                    a = *reinterpret_cast<const float4*>(A + (size_t)gr * K + k0 + c4 * 4);
                __nv_bfloat16 h0 = __float2bfloat16(a.x);
                __nv_bfloat16 h1 = __float2bfloat16(a.y);
                __nv_bfloat16 h2 = __float2bfloat16(a.z);
                __nv_bfloat16 h3 = __float2bfloat16(a.w);
                __nv_bfloat16 l0 = __float2bfloat16(a.x - __bfloat162float(h0));
                __nv_bfloat16 l1 = __float2bfloat16(a.y - __bfloat162float(h1));
                __nv_bfloat16 l2 = __float2bfloat16(a.z - __bfloat162float(h2));
                __nv_bfloat16 l3 = __float2bfloat16(a.w - __bfloat162float(h3));
                uint2 uh = make_uint2(
                    ((uint32_t)__bfloat16_as_ushort(h1) << 16) | __bfloat16_as_ushort(h0),
                    ((uint32_t)__bfloat16_as_ushort(h3) << 16) | __bfloat16_as_ushort(h2));
                uint2 ul = make_uint2(
                    ((uint32_t)__bfloat16_as_ushort(l1) << 16) | __bfloat16_as_ushort(l0),
                    ((uint32_t)__bfloat16_as_ushort(l3) << 16) | __bfloat16_as_ushort(l2));
                *reinterpret_cast<uint2*>(sAh + row * LD + c4 * 4) = uh;
                *reinterpret_cast<uint2*>(sAl + row * LD + c4 * 4) = ul;
            }
        }
        // --- stage B [64 x 32] bf16 hi/lo (copy) ---
        {
            int rowb = tid >> 2;      // 0..63
            int c8 = tid & 3;         // 8-bf16 chunk
            size_t g = (size_t)(c0 + rowb) * K + k0 + c8 * 8;
            *reinterpret_cast<uint4*>(sBh + rowb * LD + c8 * 8) =
                *reinterpret_cast<const uint4*>(Bh_g + g);
            *reinterpret_cast<uint4*>(sBl + rowb * LD + c8 * 8) =
                *reinterpret_cast<const uint4*>(Bl_g + g);
        }
        __syncthreads();

#pragma unroll
        for (int kk = 0; kk < 2; kk++) {
            uint32_t ah[2][4], al[2][4], bh[2][4], bl[2][4];
#pragma unroll
            for (int im = 0; im < 2; im++) {
                uint32_t off = (uint32_t)(((wm * 32 + im * 16 + a_r) * LD + kk * 16 + a_c) * 2);
                ldsm4(ah[im][0], ah[im][1], ah[im][2], ah[im][3], aH + off);
                ldsm4(al[im][0], al[im][1], al[im][2], al[im][3], aL + off);
            }
#pragma unroll
            for (int jp = 0; jp < 2; jp++) {
                uint32_t off = (uint32_t)(((wn * 32 + jp * 16 + b_n) * LD + kk * 16 + b_k) * 2);
                ldsm4(bh[jp][0], bh[jp][1], bh[jp][2], bh[jp][3], bH + off);
                ldsm4(bl[jp][0], bl[jp][1], bl[jp][2], bl[jp][3], bL + off);
            }
#pragma unroll
            for (int im = 0; im < 2; im++)
#pragma unroll
                for (int jn = 0; jn < 4; jn++) {
                    const uint32_t* pbh = &bh[jn >> 1][(jn & 1) * 2];
                    const uint32_t* pbl = &bl[jn >> 1][(jn & 1) * 2];
                    mma_bf16(acc[im][jn], ah[im], pbh);
                    mma_bf16(acc[im][jn], ah[im], pbl);
                    mma_bf16(acc[im][jn], al[im], pbh);
                }
        }
        __syncthreads();
    }

    // --- epilogue ---
#pragma unroll
    for (int im = 0; im < 2; im++) {
        int rowa = r0 + wm * 32 + im * 16 + (lane >> 2);
        int rowb2 = rowa + 8;
#pragma unroll
        for (int jn = 0; jn < 4; jn++) {
            int col = c0 + wn * 32 + jn * 8 + (lane & 3) * 2;
            float2 bv = make_float2(0.f, 0.f);
            if (BIAS) bv = *reinterpret_cast<const float2*>(bias + col);
#pragma unroll
            for (int h = 0; h < 2; h++) {
                int row = h ? rowb2 : rowa;
                if (row >= rows) continue;
                float vx = acc[im][jn][h * 2 + 0];
                float vy = acc[im][jn][h * 2 + 1];
                if (BIAS) { vx += bv.x; vy += bv.y; }
                if (GELU) { vx = gelu_f(vx); vy = gelu_f(vy); }
                float* p = C + (size_t)row * ncols + col;
                if (RESID) {
                    float2 old = *reinterpret_cast<const float2*>(p);
                    vx += old.x; vy += old.y;
                }
                *reinterpret_cast<float2*>(p) = make_float2(vx, vy);
            }
        }
    }
}

// ---------------------------------------------------------------------------
// Embedding init: x[n,d] = sum_h table[z[n],h] * W[h,d] + b[d]
// ---------------------------------------------------------------------------
__global__ void embed_kernel(const int* __restrict__ z,
                             const float* __restrict__ table,
                             const float* __restrict__ W,
                             const float* __restrict__ b,
                             float* __restrict__ x, int N) {
    int n = blockIdx.x;
    if (n >= N) return;
    int d = threadIdx.x;
    int t = z[n];
    float acc = b[d];
#pragma unroll
    for (int h = 0; h < 5; h++) acc += table[t * 5 + h] * W[h * 256 + d];
    x[(size_t)n * 256 + d] = acc;
}

// ---------------------------------------------------------------------------
// Bessel RBF with polynomial envelope (p=5)
// ---------------------------------------------------------------------------
__global__ void rbf_kernel(const int* __restrict__ ei,
                           const float* __restrict__ pos,
                           const float* __restrict__ freqs,
                           int E) {
    int e = blockIdx.x * blockDim.x + threadIdx.x;
    if (e >= E) return;
    int i = ei[e];
    int j = ei[E + e];
    float dx = pos[i * 3 + 0] - pos[j * 3 + 0];
    float dy = pos[i * 3 + 1] - pos[j * 3 + 1];
    float dz = pos[i * 3 + 2] - pos[j * 3 + 2];
    float dist = sqrtf(dx * dx + dy * dy + dz * dz + 1e-12f);
    float x = dist * 0.2f;
    float x2 = x * x;
    float x4 = x2 * x2;
    float env = 1.0f / x + (-21.0f) * x4 + 35.0f * x4 * x + (-15.0f) * x4 * x2;
#pragma unroll
    for (int r = 0; r < 12; r++)
        g_rbf[(size_t)e * 12 + r] = env * sinf(freqs[r] * x);
}

// ---------------------------------------------------------------------------
// Edge messages + scatter: 16 threads/edge, vector red.global.add.v4.f32
// ---------------------------------------------------------------------------
__global__ void edge_msg_kernel(const int* __restrict__ ei,
                                const float* __restrict__ Wrbf,  // [12,64]
                                int E) {
    __shared__ float sW[12 * 64];
    for (int t = threadIdx.x; t < 12 * 64; t += blockDim.x) sW[t] = Wrbf[t];
    __syncthreads();

    int gt = blockIdx.x * blockDim.x + threadIdx.x;
    int e = gt >> 4;
    if (e >= E) return;
    int sub = gt & 15;
    int m0 = sub * 4;

    int i = ei[e];
    int j = ei[E + e];

    float gx = 0.f, gy = 0.f, gz = 0.f, gw = 0.f;
#pragma unroll
    for (int r = 0; r < 12; r++) {
        float rv = __ldg(&g_rbf[(size_t)e * 12 + r]);
        const float* w = &sW[r * 64 + m0];
        gx = fmaf(rv, w[0], gx);
        gy = fmaf(rv, w[1], gy);
        gz = fmaf(rv, w[2], gz);
        gw = fmaf(rv, w[3], gw);
    }
    const float4 vj = *reinterpret_cast<const float4*>(g_v + (size_t)j * 64 + m0);
    float vx = vj.x * gx, vy = vj.y * gy, vz = vj.z * gz, vw = vj.w * gw;
    float* dst = g_agg + (size_t)i * 64 + m0;
    asm volatile("red.global.add.v4.f32 [%0], {%1, %2, %3, %4};"
                 :: "l"(dst), "f"(vx), "f"(vy), "f"(vz), "f"(vw) : "memory");
}

// ---------------------------------------------------------------------------
// Launcher
// ---------------------------------------------------------------------------
extern "C" void kernel_launch(void* const* d_in, const int* in_sizes, int n_in,
                              void* d_out, int out_size) {
    const int* z = (const int*)d_in[0];
    const float* pos = (const float*)d_in[1];
    const int* ei = (const int*)d_in[4];
    const float* emb_table = (const float*)d_in[5];
    const float* emb_W = (const float*)d_in[6];
    const float* emb_b = (const float*)d_in[7];
    const float* freqs = (const float*)d_in[8];
    const float* fc0_W = (const float*)d_in[9];
    const float* fc0_b = (const float*)d_in[10];
    const float* conv_Wv = (const float*)d_in[11];
    const float* conv_Wrbf = (const float*)d_in[12];
    const float* conv_Wout = (const float*)d_in[13];
    const float* fc_W = (const float*)d_in[14];
    const float* fc_b = (const float*)d_in[15];

    int N = in_sizes[1] / 3;   // 50000
    int E = in_sizes[4] / 2;   // 800000

    float* x = (float*)d_out;

    float *tmp, *vbuf, *agg;
    __nv_bfloat16 *wh, *wl;
    cudaGetSymbolAddress((void**)&tmp, g_tmp);
    cudaGetSymbolAddress((void**)&vbuf, g_v);
    cudaGetSymbolAddress((void**)&agg, g_agg);
    cudaGetSymbolAddress((void**)&wh, g_wh);
    cudaGetSymbolAddress((void**)&wl, g_wl);

    // ---- weight conversion (hi/lo bf16, transposed) ----
    // layout: fc0 l0,l1 @ 0,65536 ; fc (n,l) @ (2+2n+l)*65536 ;
    //         Wv n @ 655360 + n*16384 ; Wout n @ 655360+65536 + n*16384
    {
        int T = 2 * 65536;
        conv_w_kernel<<<(T + 255) / 256, 256>>>(fc0_W, wh, wl, 256, 256, T);
        T = 8 * 65536;
        conv_w_kernel<<<(T + 255) / 256, 256>>>(fc_W, wh + 2 * 65536, wl + 2 * 65536, 256, 256, T);
        T = 4 * 16384;
        conv_w_kernel<<<(T + 255) / 256, 256>>>(conv_Wv, wh + 655360, wl + 655360, 256, 64, T);
        conv_w_kernel<<<(T + 255) / 256, 256>>>(conv_Wout, wh + 655360 + 65536,
                                                wl + 655360 + 65536, 64, 256, T);
    }

    dim3 gridD(4, (N + 127) / 128);   // ncols=256 (BN=64)
    dim3 gridM(1, (N + 127) / 128);   // ncols=64

    // 1. init embedding
    embed_kernel<<<N, 256>>>(z, emb_table, emb_W, emb_b, x, N);

    // 2. init FC block: x = gelu(gelu(x@W0+b0)@W1+b1)
    mma_gemm<true, true, false><<<gridD, 256>>>(x, wh, wl, fc0_b, tmp, N, 256, 256);
    mma_gemm<true, true, false><<<gridD, 256>>>(tmp, wh + 65536, wl + 65536,
                                                fc0_b + 256, x, N, 256, 256);

    // 3. radial basis
    rbf_kernel<<<(E + 255) / 256, 256>>>(ei, pos, freqs, E);

    // 4. interaction blocks
    for (int n = 0; n < 4; n++) {
        cudaMemsetAsync(agg, 0, (size_t)N * 64 * sizeof(float));

        // v = x @ Wv[n]
        mma_gemm<false, false, false><<<gridM, 256>>>(
            x, wh + 655360 + n * 16384, wl + 655360 + n * 16384, nullptr,
            vbuf, N, 256, 64);

        // gated messages + vector-red scatter
        edge_msg_kernel<<<(E * 16 + 255) / 256, 256>>>(
            ei, conv_Wrbf + (size_t)n * 12 * 64, E);

        // x = x + agg @ Wout[n]
        mma_gemm<false, false, true><<<gridD, 256>>>(
            agg, wh + 655360 + 65536 + n * 16384, wl + 655360 + 65536 + n * 16384,
            nullptr, x, N, 64, 256);

        // x = x + fc_block(x)
        const __nv_bfloat16* W0h = wh + (size_t)(2 + 2 * n) * 65536;
        const __nv_bfloat16* W0l = wl + (size_t)(2 + 2 * n) * 65536;
        const __nv_bfloat16* W1h = wh + (size_t)(3 + 2 * n) * 65536;
        const __nv_bfloat16* W1l = wl + (size_t)(3 + 2 * n) * 65536;
        const float* b0 = fc_b + (size_t)n * 2 * 256;
        const float* b1 = b0 + 256;
        mma_gemm<true, true, false><<<gridD, 256>>>(x, W0h, W0l, b0, tmp, N, 256, 256);
        mma_gemm<true, true, true><<<gridD, 256>>>(tmp, W1h, W1l, b1, x, N, 256, 256);
    }
}